// round 2
// baseline (speedup 1.0000x reference)
#include <cuda_runtime.h>
#include <math.h>

#define N 8192
#define D 512
#define KSEL 16

#define BM 128
#define BN 128
#define BK 8
#define TM 8
#define TN 8
// 256 threads = (BM/TM) * (BN/TN) = 16 x 16

// ---------------------------------------------------------------------------
// Kernel 1: sim = X * X^T  (fp32 SIMT tiled GEMM, NT form)
// C[i][j] = sum_k X[i][k] * X[j][k]
// ---------------------------------------------------------------------------
__global__ __launch_bounds__(256) void gemm_xxT_kernel(
    const float* __restrict__ X, float* __restrict__ C)
{
    __shared__ float As[BK][BM];
    __shared__ float Bs[BK][BN];

    const int bx = blockIdx.x;  // col block
    const int by = blockIdx.y;  // row block
    const int tid = threadIdx.x;
    const int tx = tid & 15;    // 0..15 (col direction)
    const int ty = tid >> 4;    // 0..15 (row direction)

    // Global load mapping: one float4 of A and one of B per thread per k-tile.
    const int lrow = tid >> 1;       // 0..127
    const int lk   = (tid & 1) * 4;  // 0 or 4

    const float* Arow = X + (size_t)(by * BM + lrow) * D;
    const float* Brow = X + (size_t)(bx * BN + lrow) * D;

    float acc[TM][TN];
#pragma unroll
    for (int i = 0; i < TM; i++)
#pragma unroll
        for (int j = 0; j < TN; j++) acc[i][j] = 0.0f;

    for (int k0 = 0; k0 < D; k0 += BK) {
        float4 a = *(const float4*)(Arow + k0 + lk);
        float4 b = *(const float4*)(Brow + k0 + lk);
        As[lk + 0][lrow] = a.x;
        As[lk + 1][lrow] = a.y;
        As[lk + 2][lrow] = a.z;
        As[lk + 3][lrow] = a.w;
        Bs[lk + 0][lrow] = b.x;
        Bs[lk + 1][lrow] = b.y;
        Bs[lk + 2][lrow] = b.z;
        Bs[lk + 3][lrow] = b.w;
        __syncthreads();

#pragma unroll
        for (int k = 0; k < BK; k++) {
            float ar[TM], br[TN];
#pragma unroll
            for (int i = 0; i < TM; i++) ar[i] = As[k][ty * TM + i];
#pragma unroll
            for (int j = 0; j < TN; j++) br[j] = Bs[k][tx * TN + j];
#pragma unroll
            for (int i = 0; i < TM; i++)
#pragma unroll
                for (int j = 0; j < TN; j++)
                    acc[i][j] = fmaf(ar[i], br[j], acc[i][j]);
        }
        __syncthreads();
    }

    // Store 8x8 tile as two float4s per row.
#pragma unroll
    for (int i = 0; i < TM; i++) {
        size_t row = (size_t)(by * BM + ty * TM + i);
        float* cp = C + row * N + (bx * BN + tx * TN);
        float4 v0 = make_float4(acc[i][0], acc[i][1], acc[i][2], acc[i][3]);
        float4 v1 = make_float4(acc[i][4], acc[i][5], acc[i][6], acc[i][7]);
        *(float4*)(cp + 0) = v0;
        *(float4*)(cp + 4) = v1;
    }
}

// ---------------------------------------------------------------------------
// Kernel 2: per-row top-16 select + sparsify (in place on the adj region).
// One CTA per row. Row copied to smem, 16x iterative argmax with
// lowest-index tie-break (matches jax.lax.top_k), then zero row and scatter.
// ---------------------------------------------------------------------------
__global__ __launch_bounds__(256) void topk_row_kernel(float* __restrict__ adj)
{
    __shared__ float vals[N];           // 32 KB working copy
    __shared__ float rv[256];
    __shared__ int   ri[256];
    __shared__ float selv[KSEL];
    __shared__ int   seli[KSEL];

    const int row = blockIdx.x;
    float* rowp = adj + (size_t)row * N;
    const int tid = threadIdx.x;

    // Load row into smem (float4).
    for (int j = tid * 4; j < N; j += 256 * 4)
        *(float4*)&vals[j] = *(const float4*)&rowp[j];
    __syncthreads();

    for (int it = 0; it < KSEL; it++) {
        float best = -INFINITY;
        int bi = -1;
        for (int j = tid; j < N; j += 256) {
            float v = vals[j];
            if (v > best) { best = v; bi = j; }  // first (lowest) idx wins ties
        }
        rv[tid] = best;
        ri[tid] = bi;
        __syncthreads();
        if (tid == 0) {
            float b = rv[0];
            int idx = ri[0];
            for (int t = 1; t < 256; t++) {
                if (rv[t] > b || (rv[t] == b && ri[t] < idx)) {
                    b = rv[t];
                    idx = ri[t];
                }
            }
            selv[it] = b;
            seli[it] = idx;
            vals[idx] = -INFINITY;  // mask for next iteration
        }
        __syncthreads();
    }

    // Zero the whole row, then scatter the 16 kept values.
    const float4 z = make_float4(0.f, 0.f, 0.f, 0.f);
    for (int j = tid * 4; j < N; j += 256 * 4)
        *(float4*)&rowp[j] = z;
    __syncthreads();
    if (tid < KSEL)
        rowp[seli[tid]] = selv[tid];
}

// ---------------------------------------------------------------------------
// Launch
// ---------------------------------------------------------------------------
extern "C" void kernel_launch(void* const* d_in, const int* in_sizes, int n_in,
                              void* d_out, int out_size)
{
    const float* x = (const float*)d_in[0];
    float* out = (float*)d_out;

    // Output layout: [ x (N*D floats) | adj (N*N floats) ]
    float* out_x   = out;
    float* out_adj = out + (size_t)N * D;

    // 1) Copy x through.
    cudaMemcpyAsync(out_x, x, (size_t)N * D * sizeof(float),
                    cudaMemcpyDeviceToDevice, 0);

    // 2) sim = x @ x^T into the adj region.
    dim3 grid(N / BN, N / BM);
    gemm_xxT_kernel<<<grid, 256>>>(x, out_adj);

    // 3) Per-row top-16 sparsification in place.
    topk_row_kernel<<<N, 256>>>(out_adj);
}